// round 5
// baseline (speedup 1.0000x reference)
#include <cuda_runtime.h>
#include <cstdint>
#include <cstddef>

#define NUM_EXPERTS 8
#define DIM 2048
#define HIDDEN 7168
#define NTOK 2048              // B*S
#define NSLOT (NTOK * 2)

// ---------------- device scratch (static: no allocations allowed) ----------
__device__ int   g_cnt[NUM_EXPERTS];
__device__ int   g_tok[NUM_EXPERTS][NTOK];
__device__ int   g_slot[NUM_EXPERTS][NTOK];
__device__ float g_wt[NUM_EXPERTS][NTOK];
__device__ float g_h[(size_t)NSLOT * HIDDEN];   // ~117 MB SwiGLU activations

// ---------------- helpers ---------------------------------------------------
__device__ __forceinline__ unsigned f2tf(float v) {
    unsigned r;
    asm("cvt.rna.tf32.f32 %0, %1;" : "=r"(r) : "f"(v));
    return r;
}

__device__ __forceinline__ void mma8(float* c, const unsigned* a, unsigned b0, unsigned b1) {
    asm("mma.sync.aligned.m16n8k8.row.col.f32.tf32.tf32.f32 "
        "{%0,%1,%2,%3}, {%4,%5,%6,%7}, {%8,%9}, {%0,%1,%2,%3};"
        : "+f"(c[0]), "+f"(c[1]), "+f"(c[2]), "+f"(c[3])
        : "r"(a[0]), "r"(a[1]), "r"(a[2]), "r"(a[3]), "r"(b0), "r"(b1));
}

// ---------------- kernel 0: reset counters + zero output --------------------
__global__ void zero_kernel(float* __restrict__ out, int n) {
    int idx = blockIdx.x * blockDim.x + threadIdx.x;
    if (idx < NUM_EXPERTS) g_cnt[idx] = 0;
    for (int i = idx; i < n; i += gridDim.x * blockDim.x) out[i] = 0.f;
}

// ---------------- kernel 1: gating (1 warp per token) -----------------------
__global__ void gate_kernel(const float* __restrict__ x, const float* __restrict__ Wg) {
    int lane = threadIdx.x & 31;
    int t = blockIdx.x * (blockDim.x >> 5) + (threadIdx.x >> 5);
    if (t >= NTOK) return;
    const float* xr = x + (size_t)t * DIM;

    float acc[NUM_EXPERTS];
#pragma unroll
    for (int e = 0; e < NUM_EXPERTS; e++) acc[e] = 0.f;

    for (int d = lane; d < DIM; d += 32) {
        float xv = xr[d];
        const float* wr = Wg + d * NUM_EXPERTS;
#pragma unroll
        for (int e = 0; e < NUM_EXPERTS; e++) acc[e] += xv * wr[e];
    }
#pragma unroll
    for (int e = 0; e < NUM_EXPERTS; e++) {
#pragma unroll
        for (int s = 16; s > 0; s >>= 1)
            acc[e] += __shfl_xor_sync(0xffffffffu, acc[e], s);
    }
    if (lane == 0) {
        int b0 = 0;
#pragma unroll
        for (int e = 1; e < NUM_EXPERTS; e++) if (acc[e] > acc[b0]) b0 = e;
        int b1 = (b0 == 0) ? 1 : 0;
#pragma unroll
        for (int e = 0; e < NUM_EXPERTS; e++) if (e != b0 && acc[e] > acc[b1]) b1 = e;
        float d1  = expf(acc[b1] - acc[b0]);
        float inv = 1.f / (1.f + d1);
        int p0 = atomicAdd(&g_cnt[b0], 1);
        g_tok[b0][p0] = t; g_slot[b0][p0] = 2 * t;     g_wt[b0][p0] = inv;
        int p1 = atomicAdd(&g_cnt[b1], 1);
        g_tok[b1][p1] = t; g_slot[b1][p1] = 2 * t + 1; g_wt[b1][p1] = d1 * inv;
    }
}

// ============================================================================
// kernel 2: grouped dual GEMM (x@w1, x@w3) + SwiGLU -> g_h
// BM=128, BN=64 (dual B), BK=16, 256 threads, 2-stage smem double buffer.
// ============================================================================
#define BMH 128
#define BNH 64
#define BKH 16

__global__ __launch_bounds__(256, 2)
void gemm_h_kernel(const float* __restrict__ x,
                   const float* __restrict__ w1,
                   const float* __restrict__ w3) {
    int e  = blockIdx.z;
    int Ne = g_cnt[e];
    int m0 = blockIdx.x * BMH;
    if (m0 >= Ne) return;
    int n0 = blockIdx.y * BNH;

    __shared__ __align__(16) unsigned As [2][BMH][BKH + 4];
    __shared__ __align__(16) unsigned B1s[2][BKH][BNH + 8];
    __shared__ __align__(16) unsigned B3s[2][BKH][BNH + 8];
    __shared__ int row_tok[BMH];

    int tid = threadIdx.x;
    if (tid < BMH) {
        int r = m0 + tid;
        row_tok[tid] = (r < Ne) ? g_tok[e][r] : -1;
    }
    __syncthreads();

    const float* W1 = w1 + (size_t)e * DIM * HIDDEN + n0;
    const float* W3 = w3 + (size_t)e * DIM * HIDDEN + n0;

    // loader geometry
    int lar = tid >> 2;            // A rows: lar and lar+64
    int lac = (tid & 3) * 4;       // 4 consecutive k
    int lbr = tid >> 4;            // B row 0..15
    int lbc = (tid & 15) * 4;      // 4 consecutive n

    int t0 = row_tok[lar], t1 = row_tok[lar + 64];
    const float* xa0 = (t0 >= 0) ? x + (size_t)t0 * DIM + lac : nullptr;
    const float* xa1 = (t1 >= 0) ? x + (size_t)t1 * DIM + lac : nullptr;

    float4 ra0, ra1, rb1, rb3;
    const float4 z4 = make_float4(0.f, 0.f, 0.f, 0.f);

    auto LD = [&](int k0) {
        ra0 = xa0 ? *(const float4*)(xa0 + k0) : z4;
        ra1 = xa1 ? *(const float4*)(xa1 + k0) : z4;
        size_t off = (size_t)(k0 + lbr) * HIDDEN + lbc;
        rb1 = *(const float4*)(W1 + off);
        rb3 = *(const float4*)(W3 + off);
    };
    auto ST = [&](int st) {
        *(uint4*)&As [st][lar     ][lac] = make_uint4(f2tf(ra0.x), f2tf(ra0.y), f2tf(ra0.z), f2tf(ra0.w));
        *(uint4*)&As [st][lar + 64][lac] = make_uint4(f2tf(ra1.x), f2tf(ra1.y), f2tf(ra1.z), f2tf(ra1.w));
        *(uint4*)&B1s[st][lbr][lbc]      = make_uint4(f2tf(rb1.x), f2tf(rb1.y), f2tf(rb1.z), f2tf(rb1.w));
        *(uint4*)&B3s[st][lbr][lbc]      = make_uint4(f2tf(rb3.x), f2tf(rb3.y), f2tf(rb3.z), f2tf(rb3.w));
    };

    int lane = tid & 31, warp = tid >> 5;
    int m_base = (warp >> 2) * 64;   // 2 warp-rows
    int n_base = (warp & 3) * 16;    // 4 warp-cols

    float acc1[4][2][4], acc3[4][2][4];
#pragma unroll
    for (int a = 0; a < 4; a++)
#pragma unroll
        for (int b = 0; b < 2; b++)
#pragma unroll
            for (int c = 0; c < 4; c++) { acc1[a][b][c] = 0.f; acc3[a][b][c] = 0.f; }

    const int KT = DIM / BKH;   // 128
    LD(0); ST(0);
    __syncthreads();

    for (int kt = 0; kt < KT; kt++) {
        int nxt = kt + 1;
        if (nxt < KT) LD(nxt * BKH);
        int st = kt & 1;
#pragma unroll
        for (int ks = 0; ks < 2; ks++) {
            unsigned a[4][4];
#pragma unroll
            for (int mt = 0; mt < 4; mt++) {
                int ar = m_base + mt * 16 + (lane >> 2);
                int ac = ks * 8 + (lane & 3);
                a[mt][0] = As[st][ar][ac];
                a[mt][1] = As[st][ar + 8][ac];
                a[mt][2] = As[st][ar][ac + 4];
                a[mt][3] = As[st][ar + 8][ac + 4];
            }
#pragma unroll
            for (int nt = 0; nt < 2; nt++) {
                int bk = ks * 8 + (lane & 3);
                int bc = n_base + nt * 8 + (lane >> 2);
                unsigned b0 = B1s[st][bk][bc], b1 = B1s[st][bk + 4][bc];
                unsigned c0 = B3s[st][bk][bc], c1 = B3s[st][bk + 4][bc];
#pragma unroll
                for (int mt = 0; mt < 4; mt++) {
                    mma8(acc1[mt][nt], a[mt], b0, b1);
                    mma8(acc3[mt][nt], a[mt], c0, c1);
                }
            }
        }
        if (nxt < KT) ST(nxt & 1);
        __syncthreads();
    }

    // epilogue: h = silu(x@w1) * (x@w3) -> g_h[slot]
#pragma unroll
    for (int mt = 0; mt < 4; mt++) {
        int r_lo = m0 + m_base + mt * 16 + (lane >> 2);
        int r_hi = r_lo + 8;
        int s_lo = (r_lo < Ne) ? g_slot[e][r_lo] : -1;
        int s_hi = (r_hi < Ne) ? g_slot[e][r_hi] : -1;
#pragma unroll
        for (int nt = 0; nt < 2; nt++) {
            int col = n0 + n_base + nt * 8 + 2 * (lane & 3);
            if (s_lo >= 0) {
                float* hp = g_h + (size_t)s_lo * HIDDEN + col;
                float a0 = acc1[mt][nt][0], a1 = acc1[mt][nt][1];
                hp[0] = (a0 / (1.f + __expf(-a0))) * acc3[mt][nt][0];
                hp[1] = (a1 / (1.f + __expf(-a1))) * acc3[mt][nt][1];
            }
            if (s_hi >= 0) {
                float* hp = g_h + (size_t)s_hi * HIDDEN + col;
                float a2 = acc1[mt][nt][2], a3 = acc1[mt][nt][3];
                hp[0] = (a2 / (1.f + __expf(-a2))) * acc3[mt][nt][2];
                hp[1] = (a3 / (1.f + __expf(-a3))) * acc3[mt][nt][3];
            }
        }
    }
}

// ============================================================================
// kernel 3: grouped GEMM2 (h @ w2) + weighted combine (atomicAdd, 2 adds/elem)
// BM=128, BN=128, BK=16, 256 threads, 2-stage smem double buffer.
// ============================================================================
#define BM2 128
#define BN2 128
#define BK2 16

__global__ __launch_bounds__(256, 2)
void gemm2_kernel(const float* __restrict__ w2, float* __restrict__ out) {
    int e  = blockIdx.z;
    int Ne = g_cnt[e];
    int m0 = blockIdx.x * BM2;
    if (m0 >= Ne) return;
    int n0 = blockIdx.y * BN2;

    __shared__ __align__(16) unsigned As[2][BM2][BK2 + 4];
    __shared__ __align__(16) unsigned Bs[2][BK2][BN2 + 8];
    __shared__ int   row_tk[BM2];
    __shared__ float row_wt[BM2];
    __shared__ int   row_sl[BM2];

    int tid = threadIdx.x;
    if (tid < BM2) {
        int r = m0 + tid;
        if (r < Ne) {
            row_sl[tid] = g_slot[e][r];
            row_tk[tid] = g_tok[e][r];
            row_wt[tid] = g_wt[e][r];
        } else {
            row_sl[tid] = -1; row_tk[tid] = -1; row_wt[tid] = 0.f;
        }
    }
    __syncthreads();

    const float* W2 = w2 + (size_t)e * HIDDEN * DIM + n0;

    int lar = tid >> 2;            // A rows lar, lar+64
    int lac = (tid & 3) * 4;
    int lbr = tid >> 5;            // B rows lbr, lbr+8
    int lbc = (tid & 31) * 4;

    int s0 = row_sl[lar], s1 = row_sl[lar + 64];
    const float* ha0 = (s0 >= 0) ? g_h + (size_t)s0 * HIDDEN + lac : nullptr;
    const float* ha1 = (s1 >= 0) ? g_h + (size_t)s1 * HIDDEN + lac : nullptr;

    float4 ra0, ra1, rb0, rb1;
    const float4 z4 = make_float4(0.f, 0.f, 0.f, 0.f);

    auto LD = [&](int k0) {
        ra0 = ha0 ? *(const float4*)(ha0 + k0) : z4;
        ra1 = ha1 ? *(const float4*)(ha1 + k0) : z4;
        rb0 = *(const float4*)(W2 + (size_t)(k0 + lbr) * DIM + lbc);
        rb1 = *(const float4*)(W2 + (size_t)(k0 + lbr + 8) * DIM + lbc);
    };
    auto ST = [&](int st) {
        *(uint4*)&As[st][lar     ][lac] = make_uint4(f2tf(ra0.x), f2tf(ra0.y), f2tf(ra0.z), f2tf(ra0.w));
        *(uint4*)&As[st][lar + 64][lac] = make_uint4(f2tf(ra1.x), f2tf(ra1.y), f2tf(ra1.z), f2tf(ra1.w));
        *(uint4*)&Bs[st][lbr    ][lbc] = make_uint4(f2tf(rb0.x), f2tf(rb0.y), f2tf(rb0.z), f2tf(rb0.w));
        *(uint4*)&Bs[st][lbr + 8][lbc] = make_uint4(f2tf(rb1.x), f2tf(rb1.y), f2tf(rb1.z), f2tf(rb1.w));
    };

    int lane = tid & 31, warp = tid >> 5;
    int m_base = (warp >> 2) * 64;
    int n_base = (warp & 3) * 32;

    float acc[4][4][4];
#pragma unroll
    for (int a = 0; a < 4; a++)
#pragma unroll
        for (int b = 0; b < 4; b++)
#pragma unroll
            for (int c = 0; c < 4; c++) acc[a][b][c] = 0.f;

    const int KT = HIDDEN / BK2;   // 448
    LD(0); ST(0);
    __syncthreads();

    for (int kt = 0; kt < KT; kt++) {
        int nxt = kt + 1;
        if (nxt < KT) LD(nxt * BK2);
        int st = kt & 1;
#pragma unroll
        for (int ks = 0; ks < 2; ks++) {
            unsigned a[4][4];
#pragma unroll
            for (int mt = 0; mt < 4; mt++) {
                int ar = m_base + mt * 16 + (lane >> 2);
                int ac = ks * 8 + (lane & 3);
                a[mt][0] = As[st][ar][ac];
                a[mt][1] = As[st][ar + 8][ac];
                a[mt][2] = As[st][ar][ac + 4];
                a[mt][3] = As[st][ar + 8][ac + 4];
            }
#pragma unroll
            for (int nt = 0; nt < 4; nt++) {
                int bk = ks * 8 + (lane & 3);
                int bc = n_base + nt * 8 + (lane >> 2);
                unsigned b0 = Bs[st][bk][bc], b1 = Bs[st][bk + 4][bc];
#pragma unroll
                for (int mt = 0; mt < 4; mt++)
                    mma8(acc[mt][nt], a[mt], b0, b1);
            }
        }
        if (nxt < KT) ST(nxt & 1);
        __syncthreads();
    }

    // epilogue: out[token] += weight * result
#pragma unroll
    for (int mt = 0; mt < 4; mt++) {
        int rr_lo = m_base + mt * 16 + (lane >> 2);
        int rr_hi = rr_lo + 8;
        int t_lo = row_tk[rr_lo];
        int t_hi = row_tk[rr_hi];
        float w_lo = row_wt[rr_lo];
        float w_hi = row_wt[rr_hi];
#pragma unroll
        for (int nt = 0; nt < 4; nt++) {
            int col = n0 + n_base + nt * 8 + 2 * (lane & 3);
            if (t_lo >= 0) {
                atomicAdd(&out[(size_t)t_lo * DIM + col],     w_lo * acc[mt][nt][0]);
                atomicAdd(&out[(size_t)t_lo * DIM + col + 1], w_lo * acc[mt][nt][1]);
            }
            if (t_hi >= 0) {
                atomicAdd(&out[(size_t)t_hi * DIM + col],     w_hi * acc[mt][nt][2]);
                atomicAdd(&out[(size_t)t_hi * DIM + col + 1], w_hi * acc[mt][nt][3]);
            }
        }
    }
}

// ---------------- launch -----------------------------------------------------
extern "C" void kernel_launch(void* const* d_in, const int* in_sizes, int n_in,
                              void* d_out, int out_size) {
    const float* x  = (const float*)d_in[0];   // [2,1024,2048]
    const float* Wg = (const float*)d_in[1];   // [2048,8]
    const float* w1 = (const float*)d_in[2];   // [8,2048,7168]
    const float* w3 = (const float*)d_in[3];   // [8,2048,7168]
    const float* w2 = (const float*)d_in[4];   // [8,7168,2048]
    float* out = (float*)d_out;                // [2,1024,2048]

    zero_kernel<<<1024, 256>>>(out, out_size);
    gate_kernel<<<NTOK / 8, 256>>>(x, Wg);

    dim3 g1(NTOK / BMH, HIDDEN / BNH, NUM_EXPERTS);   // (16, 112, 8), early-exit on count
    gemm_h_kernel<<<g1, 256>>>(x, w1, w3);

    dim3 g2(NTOK / BM2, DIM / BN2, NUM_EXPERTS);      // (16, 16, 8)
    gemm2_kernel<<<g2, 256>>>(w2, out);
}

// round 7
// speedup vs baseline: 1.0405x; 1.0405x over previous
#include <cuda_runtime.h>
#include <cstdint>
#include <cstddef>

#define NE_ 8
#define DIM 2048
#define HIDDEN 7168
#define NTOK 2048

// ---------------- device scratch ----------------
__device__ int   g_cnt[NE_];
__device__ int   g_tok[NE_][NTOK];
__device__ int   g_slotA[NE_][NTOK];
__device__ float g_wt[NE_][NTOK];
__device__ float g_h[(size_t)NTOK * 2 * HIDDEN];

// ---------------- helpers ----------------
__device__ __forceinline__ uint32_t smem_u32(const void* p) {
    uint32_t a;
    asm("{ .reg .u64 t; cvta.to.shared.u64 t, %1; cvt.u32.u64 %0, t; }" : "=r"(a) : "l"(p));
    return a;
}
__device__ __forceinline__ unsigned tf32r(unsigned u) {   // f32 bits -> tf32 (RN)
    unsigned r;
    asm("cvt.rna.tf32.f32 %0, %1;" : "=r"(r) : "r"(u));
    return r;
}
__device__ __forceinline__ unsigned lds32(uint32_t a) {
    unsigned v;
    asm volatile("ld.shared.b32 %0, [%1];" : "=r"(v) : "r"(a));
    return v;
}
__device__ __forceinline__ void ldsm4(unsigned* r, uint32_t a) {
    asm volatile("ldmatrix.sync.aligned.m8n8.x4.shared.b16 {%0,%1,%2,%3}, [%4];"
                 : "=r"(r[0]), "=r"(r[1]), "=r"(r[2]), "=r"(r[3]) : "r"(a));
}
__device__ __forceinline__ void mma8(float* c, const unsigned* a, unsigned b0, unsigned b1) {
    asm("mma.sync.aligned.m16n8k8.row.col.f32.tf32.tf32.f32 "
        "{%0,%1,%2,%3}, {%4,%5,%6,%7}, {%8,%9}, {%0,%1,%2,%3};"
        : "+f"(c[0]), "+f"(c[1]), "+f"(c[2]), "+f"(c[3])
        : "r"(a[0]), "r"(a[1]), "r"(a[2]), "r"(a[3]), "r"(b0), "r"(b1));
}
#define CPA(dst, src) asm volatile("cp.async.cg.shared.global [%0], [%1], 16;" :: "r"(dst), "l"(src) : "memory")
#define CPC() asm volatile("cp.async.commit_group;" ::: "memory")
#define CPW1() asm volatile("cp.async.wait_group 1;" ::: "memory")
#define CPW0() asm volatile("cp.async.wait_group 0;" ::: "memory")

// ---------------- kernel 0: reset + zero out ----------------
__global__ void zero_kernel(float* __restrict__ out, int n) {
    int idx = blockIdx.x * blockDim.x + threadIdx.x;
    if (idx < NE_) g_cnt[idx] = 0;
    for (int i = idx; i < n; i += gridDim.x * blockDim.x) out[i] = 0.f;
}

// ---------------- kernel 1: gating ----------------
__global__ void gate_kernel(const float* __restrict__ x, const float* __restrict__ Wg) {
    int lane = threadIdx.x & 31;
    int t = blockIdx.x * (blockDim.x >> 5) + (threadIdx.x >> 5);
    if (t >= NTOK) return;
    const float* xr = x + (size_t)t * DIM;
    float acc[NE_];
#pragma unroll
    for (int e = 0; e < NE_; e++) acc[e] = 0.f;
    for (int d = lane; d < DIM; d += 32) {
        float xv = xr[d];
        const float* wr = Wg + d * NE_;
#pragma unroll
        for (int e = 0; e < NE_; e++) acc[e] += xv * wr[e];
    }
#pragma unroll
    for (int e = 0; e < NE_; e++)
#pragma unroll
        for (int s = 16; s > 0; s >>= 1) acc[e] += __shfl_xor_sync(0xffffffffu, acc[e], s);
    if (lane == 0) {
        int b0 = 0;
#pragma unroll
        for (int e = 1; e < NE_; e++) if (acc[e] > acc[b0]) b0 = e;
        int b1 = (b0 == 0) ? 1 : 0;
#pragma unroll
        for (int e = 0; e < NE_; e++) if (e != b0 && acc[e] > acc[b1]) b1 = e;
        float d1 = expf(acc[b1] - acc[b0]);
        float inv = 1.f / (1.f + d1);
        int p0 = atomicAdd(&g_cnt[b0], 1);
        g_tok[b0][p0] = t; g_slotA[b0][p0] = 2 * t;     g_wt[b0][p0] = inv;
        int p1 = atomicAdd(&g_cnt[b1], 1);
        g_tok[b1][p1] = t; g_slotA[b1][p1] = 2 * t + 1; g_wt[b1][p1] = d1 * inv;
    }
}

// ============================================================================
// GEMM1: dual (x@w1, x@w3) + SwiGLU -> g_h.  BM=128, BN=64(x2), BK=16.
// smem/stage: A 128x80B = 10240, B1 16x288 = 4608, B3 4608 -> 19456.
// ============================================================================
#define S1 19456
#define KT1 (DIM / 16)

__global__ __launch_bounds__(256)
void gemm1_k(const float* __restrict__ x, const float* __restrict__ w1,
             const float* __restrict__ w3) {
    int e = blockIdx.z, Ne = g_cnt[e];
    int m0 = blockIdx.x * 128;
    if (m0 >= Ne) return;
    int n0 = blockIdx.y * 64;

    extern __shared__ __align__(128) char sm[];
    uint32_t sb = smem_u32(sm);
    __shared__ int rtok[128], rslot[128];

    int tid = threadIdx.x, warp = tid >> 5, lane = tid & 31;
    if (tid < 128) {
        int r = m0 + tid;
        rtok[tid]  = (r < Ne) ? g_tok[e][r] : 0;
        rslot[tid] = (r < Ne) ? g_slotA[e][r] : -1;
    }
    __syncthreads();

    // ---- loaders ----
    int am = tid >> 1, ak = tid & 1;                       // A: row, 32B half
    const float* asrc = x + (size_t)rtok[am] * DIM + ak * 8;
    uint32_t adst = sb + am * 80 + ak * 32;
    int bt = tid & 127, bmat = tid >> 7;
    int bk = bt >> 3, bq = (bt & 7) * 2;                   // B: k-row, 2 chunks of 4n
    const float* bsrc = (bmat ? w3 : w1) + (size_t)e * DIM * HIDDEN + n0
                        + (size_t)bk * HIDDEN + bq * 4;
    uint32_t bdst = sb + 10240 + bmat * 4608 + bk * 288 + bq * 16;

    auto fill = [&](int s, int k0) {
        uint32_t so = (uint32_t)s * S1;
        CPA(adst + so,      asrc + k0);
        CPA(adst + so + 16, asrc + k0 + 4);
        const float* bs = bsrc + (size_t)k0 * HIDDEN;
        CPA(bdst + so,      bs);
        CPA(bdst + so + 16, bs + 4);
    };

    // ---- mma geometry ----
    int m_base = (warp >> 2) * 64, n_base = (warp & 3) * 16;
    int lrow = (lane & 7) + ((lane >> 3) & 1) * 8;
    uint32_t abase = sb + (m_base + lrow) * 80 + (lane >> 4) * 16;
    uint32_t bcol  = (uint32_t)(n_base + (lane >> 2)) * 4;
    uint32_t brow  = (uint32_t)(lane & 3) * 288;

    float acc1[4][2][4], acc3[4][2][4];
#pragma unroll
    for (int a = 0; a < 4; a++)
#pragma unroll
        for (int b = 0; b < 2; b++)
#pragma unroll
            for (int c = 0; c < 4; c++) { acc1[a][b][c] = 0.f; acc3[a][b][c] = 0.f; }

    fill(0, 0); CPC();
    fill(1, 16); CPC();
    CPW1(); __syncthreads();

    int s = 0, fs = 2;
    for (int kt = 0; kt < KT1; kt++) {
        uint32_t so = (uint32_t)s * S1;
#pragma unroll
        for (int ks = 0; ks < 2; ks++) {
            unsigned a[4][4];
#pragma unroll
            for (int mt = 0; mt < 4; mt++) {
                ldsm4(a[mt], abase + so + mt * 1280 + ks * 32);
#pragma unroll
                for (int j = 0; j < 4; j++) a[mt][j] = tf32r(a[mt][j]);
            }
            uint32_t bb = sb + so + 10240 + ks * 8 * 288 + brow + bcol;
#pragma unroll
            for (int nt = 0; nt < 2; nt++) {
                uint32_t ba = bb + nt * 32;
                unsigned b0 = tf32r(lds32(ba)),        b1 = tf32r(lds32(ba + 4 * 288));
                unsigned c0 = tf32r(lds32(ba + 4608)), c1 = tf32r(lds32(ba + 4608 + 4 * 288));
#pragma unroll
                for (int mt = 0; mt < 4; mt++) {
                    mma8(acc1[mt][nt], a[mt], b0, b1);
                    mma8(acc3[mt][nt], a[mt], c0, c1);
                }
            }
        }
        int nk = kt + 2;
        if (nk < KT1) fill(fs, nk * 16);
        CPC();
        CPW1(); __syncthreads();
        s = (s == 2) ? 0 : s + 1;
        fs = (fs == 2) ? 0 : fs + 1;
    }
    CPW0();

    // epilogue: silu(y1)*y3 -> g_h[slot]
#pragma unroll
    for (int mt = 0; mt < 4; mt++) {
        int mloc = m_base + mt * 16 + (lane >> 2);
        int s_lo = rslot[mloc], s_hi = rslot[mloc + 8];
#pragma unroll
        for (int nt = 0; nt < 2; nt++) {
            int col = n0 + n_base + nt * 8 + 2 * (lane & 3);
            if (s_lo >= 0) {
                float* hp = g_h + (size_t)s_lo * HIDDEN + col;
                float a0 = acc1[mt][nt][0], a1 = acc1[mt][nt][1];
                hp[0] = a0 / (1.f + __expf(-a0)) * acc3[mt][nt][0];
                hp[1] = a1 / (1.f + __expf(-a1)) * acc3[mt][nt][1];
            }
            if (s_hi >= 0) {
                float* hp = g_h + (size_t)s_hi * HIDDEN + col;
                float a2 = acc1[mt][nt][2], a3 = acc1[mt][nt][3];
                hp[0] = a2 / (1.f + __expf(-a2)) * acc3[mt][nt][2];
                hp[1] = a3 / (1.f + __expf(-a3)) * acc3[mt][nt][3];
            }
        }
    }
}

// ============================================================================
// GEMM2: out += wt * (h @ w2).  BM=128, BN=128, BK=16.
// smem/stage: A 10240, B 16x544 = 8704 -> 18944.
// ============================================================================
#define S2 18944
#define KT2 (HIDDEN / 16)

__global__ __launch_bounds__(256)
void gemm2_k(const float* __restrict__ w2, float* __restrict__ out) {
    int e = blockIdx.z, Ne = g_cnt[e];
    int m0 = blockIdx.x * 128;
    if (m0 >= Ne) return;
    int n0 = blockIdx.y * 128;

    extern __shared__ __align__(128) char sm[];
    uint32_t sb = smem_u32(sm);
    __shared__ int rtok[128], rsl[128];
    __shared__ float rwt[128];

    int tid = threadIdx.x, warp = tid >> 5, lane = tid & 31;
    if (tid < 128) {
        int r = m0 + tid;
        if (r < Ne) { rtok[tid] = g_tok[e][r]; rsl[tid] = g_slotA[e][r]; rwt[tid] = g_wt[e][r]; }
        else        { rtok[tid] = -1; rsl[tid] = 0; rwt[tid] = 0.f; }
    }
    __syncthreads();

    int am = tid >> 1, ak = tid & 1;
    const float* asrc = g_h + (size_t)rsl[am] * HIDDEN + ak * 8;
    uint32_t adst = sb + am * 80 + ak * 32;
    int bk = tid >> 4, bq = (tid & 15) * 2;
    const float* bsrc = w2 + (size_t)e * HIDDEN * DIM + n0 + (size_t)bk * DIM + bq * 4;
    uint32_t bdst = sb + 10240 + bk * 544 + bq * 16;

    auto fill = [&](int s, int k0) {
        uint32_t so = (uint32_t)s * S2;
        CPA(adst + so,      asrc + k0);
        CPA(adst + so + 16, asrc + k0 + 4);
        const float* bs = bsrc + (size_t)k0 * DIM;
        CPA(bdst + so,      bs);
        CPA(bdst + so + 16, bs + 4);
    };

    int m_base = (warp >> 2) * 64, n_base = (warp & 3) * 32;
    int lrow = (lane & 7) + ((lane >> 3) & 1) * 8;
    uint32_t abase = sb + (m_base + lrow) * 80 + (lane >> 4) * 16;
    uint32_t bcol  = (uint32_t)(n_base + (lane >> 2)) * 4;
    uint32_t brow  = (uint32_t)(lane & 3) * 544;

    float acc[4][4][4];
#pragma unroll
    for (int a = 0; a < 4; a++)
#pragma unroll
        for (int b = 0; b < 4; b++)
#pragma unroll
            for (int c = 0; c < 4; c++) acc[a][b][c] = 0.f;

    fill(0, 0); CPC();
    fill(1, 16); CPC();
    CPW1(); __syncthreads();

    int s = 0, fs = 2;
    for (int kt = 0; kt < KT2; kt++) {
        uint32_t so = (uint32_t)s * S2;
#pragma unroll
        for (int ks = 0; ks < 2; ks++) {
            unsigned a[4][4];
#pragma unroll
            for (int mt = 0; mt < 4; mt++) {
                ldsm4(a[mt], abase + so + mt * 1280 + ks * 32);
#pragma unroll
                for (int j = 0; j < 4; j++) a[mt][j] = tf32r(a[mt][j]);
            }
            uint32_t bb = sb + so + 10240 + ks * 8 * 544 + brow + bcol;
#pragma unroll
            for (int nt = 0; nt < 4; nt++) {
                uint32_t ba = bb + nt * 32;
                unsigned b0 = tf32r(lds32(ba)), b1 = tf32r(lds32(ba + 4 * 544));
#pragma unroll
                for (int mt = 0; mt < 4; mt++)
                    mma8(acc[mt][nt], a[mt], b0, b1);
            }
        }
        int nk = kt + 2;
        if (nk < KT2) fill(fs, nk * 16);
        CPC();
        CPW1(); __syncthreads();
        s = (s == 2) ? 0 : s + 1;
        fs = (fs == 2) ? 0 : fs + 1;
    }
    CPW0();

    // epilogue: out[token] += wt * acc
#pragma unroll
    for (int mt = 0; mt < 4; mt++) {
        int mloc = m_base + mt * 16 + (lane >> 2);
        int t_lo = rtok[mloc], t_hi = rtok[mloc + 8];
        float w_lo = rwt[mloc], w_hi = rwt[mloc + 8];
#pragma unroll
        for (int nt = 0; nt < 4; nt++) {
            int col = n0 + n_base + nt * 8 + 2 * (lane & 3);
            if (t_lo >= 0) {
                atomicAdd(&out[(size_t)t_lo * DIM + col],     w_lo * acc[mt][nt][0]);
                atomicAdd(&out[(size_t)t_lo * DIM + col + 1], w_lo * acc[mt][nt][1]);
            }
            if (t_hi >= 0) {
                atomicAdd(&out[(size_t)t_hi * DIM + col],     w_hi * acc[mt][nt][2]);
                atomicAdd(&out[(size_t)t_hi * DIM + col + 1], w_hi * acc[mt][nt][3]);
            }
        }
    }
}

// ---------------- launch ----------------
extern "C" void kernel_launch(void* const* d_in, const int* in_sizes, int n_in,
                              void* d_out, int out_size) {
    const float* x  = (const float*)d_in[0];
    const float* Wg = (const float*)d_in[1];
    const float* w1 = (const float*)d_in[2];
    const float* w3 = (const float*)d_in[3];
    const float* w2 = (const float*)d_in[4];
    float* out = (float*)d_out;

    cudaFuncSetAttribute(gemm1_k, cudaFuncAttributeMaxDynamicSharedMemorySize, 3 * S1);
    cudaFuncSetAttribute(gemm2_k, cudaFuncAttributeMaxDynamicSharedMemorySize, 3 * S2);

    zero_kernel<<<1024, 256>>>(out, out_size);
    gate_kernel<<<NTOK / 8, 256>>>(x, Wg);

    dim3 g1(NTOK / 128, HIDDEN / 64, NE_);   // (16, 112, 8)
    gemm1_k<<<g1, 256, 3 * S1>>>(x, w1, w3);

    dim3 g2(NTOK / 128, DIM / 128, NE_);     // (16, 16, 8)
    gemm2_k<<<g2, 256, 3 * S2>>>(w2, out);
}